// round 11
// baseline (speedup 1.0000x reference)
#include <cuda_runtime.h>
#include <cstdint>
#include <math_constants.h>

#define A_NUM 9
#define KA_MAX 36864   // 64*64*9
#define N_MAX  36864
#define B_MAX  32
#define G_MAX  64
#define SELB   512
#define APT    4

struct Params { int B, G, H, W, KA, N; };
__device__ Params g_p;
__device__ int    g_rank_t[KA_MAX];          // [a][cell] inside rank or -1
__device__ float4 g_anc4[N_MAX];             // inside anchor boxes
__device__ float4 g_abox[A_NUM];
__device__ int4   g_bnd[A_NUM];              // {Lx,Rx,Ly,Ry}
__device__ uint32_t g_keyf[B_MAX * 2];
__device__ uint32_t g_keyb[B_MAX * 2];
__device__ float  g_gtmaxf[B_MAX * G_MAX];   // analytic per-gt max IoU
__device__ unsigned char g_arg[B_MAX * N_MAX];
__device__ uint32_t g_lp[B_MAX * N_MAX];     // (prio<<2) | (lab+1); 0 == lab -1
__device__ int    g_hist[B_MAX][2][256];
__device__ unsigned long long g_thr[B_MAX][2];

// ---------------- Threefry-2x32 (JAX schedule) -------------------------------
__device__ __forceinline__ uint32_t rotl32(uint32_t x, uint32_t r) {
    return __funnelshift_l(x, x, r);
}
__device__ __forceinline__ void tf2x32(uint32_t k0, uint32_t k1,
                                       uint32_t& x0, uint32_t& x1) {
    uint32_t ks2 = k0 ^ k1 ^ 0x1BD11BDAu;
    x0 += k0; x1 += k1;
    const uint32_t rA[4] = {13u, 15u, 26u, 6u};
    const uint32_t rB[4] = {17u, 29u, 16u, 24u};
#pragma unroll
    for (int i = 0; i < 4; i++) { x0 += x1; x1 = rotl32(x1, rA[i]); x1 ^= x0; }
    x0 += k1; x1 += ks2 + 1u;
#pragma unroll
    for (int i = 0; i < 4; i++) { x0 += x1; x1 = rotl32(x1, rB[i]); x1 ^= x0; }
    x0 += ks2; x1 += k0 + 2u;
#pragma unroll
    for (int i = 0; i < 4; i++) { x0 += x1; x1 = rotl32(x1, rA[i]); x1 ^= x0; }
    x0 += k0; x1 += k1 + 3u;
#pragma unroll
    for (int i = 0; i < 4; i++) { x0 += x1; x1 = rotl32(x1, rB[i]); x1 ^= x0; }
    x0 += k1; x1 += ks2 + 4u;
#pragma unroll
    for (int i = 0; i < 4; i++) { x0 += x1; x1 = rotl32(x1, rA[i]); x1 ^= x0; }
    x0 += ks2; x1 += k0 + 5u;
}

// ---------------- IoU helpers (identical op order; no FMA contraction) -------
__device__ __forceinline__ float area_fn(float x1, float y1, float x2, float y2) {
    return __fmul_rn(__fadd_rn(__fsub_rn(x2, x1), 1.0f),
                     __fadd_rn(__fsub_rn(y2, y1), 1.0f));
}

// best float iw over integer positions in [L,R] (concave in x; candidates at
// floor(+-1) of the two breakpoints; monotone rounding keeps exactness)
__device__ __forceinline__ float axis_best(float glo, float ghi,
                                           float olo, float ohi, int L, int R) {
    float t1 = __fmul_rn(__fsub_rn(glo, olo), 0.0625f);
    float t2 = __fmul_rn(__fsub_rn(ghi, ohi), 0.0625f);
    int f1 = (int)floorf(t1), f2 = (int)floorf(t2);
    int cand[6] = {f1 - 1, f1, f1 + 1, f2 - 1, f2, f2 + 1};
    float best = -1e30f;
#pragma unroll
    for (int i = 0; i < 6; i++) {
        int x = min(max(cand[i], L), R);
        float sx = __fmul_rn(16.0f, (float)x);
        float alo = __fadd_rn(sx, olo), ahi = __fadd_rn(sx, ohi);
        float iw = __fadd_rn(__fsub_rn(fminf(ahi, ghi), fmaxf(alo, glo)), 1.0f);
        best = fmaxf(best, iw);
    }
    return best;
}

__device__ __forceinline__ void compute_anchors(int H, int W,
                                                float4* sbx, int4* sb, int* Ntot) {
    const double ratios[3] = {0.5, 1.0, 2.0};
    const double scales[3] = {8.0, 16.0, 32.0};
    int nt = 0;
    for (int r = 0; r < 3; r++) {
        double ws = rint(sqrt(256.0 / ratios[r]));
        double hs = rint(ws * ratios[r]);
        for (int s = 0; s < 3; s++) {
            double Wd = ws * scales[s], Hd = hs * scales[s];
            int a = r * 3 + s;
            double x1 = 7.5 - 0.5 * (Wd - 1.0);
            double y1 = 7.5 - 0.5 * (Hd - 1.0);
            double x2 = 7.5 + 0.5 * (Wd - 1.0);
            double y2 = 7.5 + 0.5 * (Hd - 1.0);
            sbx[a] = make_float4((float)x1, (float)y1, (float)x2, (float)y2);
            int ix1 = (int)llrint(x1), iy1 = (int)llrint(y1);
            int ix2 = (int)llrint(x2), iy2 = (int)llrint(y2);
            int Lx = (ix1 < 0) ? ((-ix1 + 15) / 16) : 0;
            int Ly = (iy1 < 0) ? ((-iy1 + 15) / 16) : 0;
            int nxw = 16 * W - 1 - ix2;
            int nyh = 16 * H - 1 - iy2;
            int Rx = (nxw < 0) ? -1 : min(W - 1, nxw / 16);
            int Ry = (nyh < 0) ? -1 : min(H - 1, nyh / 16);
            sb[a] = make_int4(Lx, Rx, Ly, Ry);
            int nx = Rx - Lx + 1; if (nx < 0) nx = 0;
            int ny = Ry - Ly + 1; if (ny < 0) ny = 0;
            nt += nx * ny;
        }
    }
    *Ntot = nt;
}

// ------ K0: zero the reg region of out (last 4/5 of the buffer) --------------
__global__ void k_zero(float4* reg4, int n4) {
    int i = blockIdx.x * blockDim.x + threadIdx.x;
    if (i < n4) reg4[i] = make_float4(0.f, 0.f, 0.f, 0.f);
}

// ------ K1: setup + rank + anchor compaction + analytic gt_max + zeroing -----
__global__ void k_grid(const float* __restrict__ gt,
                       const int* pB, const int* pG, const int* pH, const int* pW) {
    __shared__ int4 sb[A_NUM];
    __shared__ float4 sbx[A_NUM];
    __shared__ int sdim[5];  // H, W, KA, B, G
    int tid = threadIdx.x;
    if (tid == 0) {
        int H = *pH, W = *pW;
        int Ntot;
        compute_anchors(H, W, sbx, sb, &Ntot);
        int KA = H * W * A_NUM;
        if (KA > KA_MAX) KA = KA_MAX;
        int B = *pB, G = *pG;
        if (B > B_MAX) B = B_MAX;
        if (G > G_MAX) G = G_MAX;
        sdim[0] = H; sdim[1] = W; sdim[2] = KA; sdim[3] = B; sdim[4] = G;
        if (blockIdx.x == 0) {
            Params p; p.B = B; p.G = G; p.H = H; p.W = W; p.KA = KA; p.N = Ntot;
            g_p = p;
            for (int a = 0; a < A_NUM; a++) { g_abox[a] = sbx[a]; g_bnd[a] = sb[a]; }
        }
    }
    __syncthreads();
    int ka = blockIdx.x * blockDim.x + tid;
    if (blockIdx.x == 0 && tid < B_MAX) {
        uint32_t h0 = 0u, h1 = (uint32_t)tid;
        tf2x32(0u, 42u, h0, h1);
        uint32_t f0 = 0u, f1 = 0u; tf2x32(h0, h1, f0, f1);
        uint32_t c0 = 0u, c1 = 1u; tf2x32(h0, h1, c0, c1);
        g_keyf[tid * 2 + 0] = f0; g_keyf[tid * 2 + 1] = f1;
        g_keyb[tid * 2 + 0] = c0; g_keyb[tid * 2 + 1] = c1;
    }
    if (ka < B_MAX * 2 * 256) ((int*)g_hist)[ka] = 0;
    const int B = sdim[3], G = sdim[4];
    // analytic per-gt max IoU
    if (ka < B_MAX * G_MAX) {
        int b = ka >> 6, g = ka & 63;
        float gm = 0.0f;
        if (b < B && g < G) {
            float4 gb = reinterpret_cast<const float4*>(gt)[(size_t)b * G + g];
            float areag = area_fn(gb.x, gb.y, gb.z, gb.w);
            for (int a = 0; a < A_NUM; a++) {
                int4 bb = sb[a];
                if (bb.y < bb.x || bb.w < bb.z) continue;
                float4 o = sbx[a];
                float bw = axis_best(gb.x, gb.z, o.x, o.z, bb.x, bb.y);
                float bh = axis_best(gb.y, gb.w, o.y, o.w, bb.z, bb.w);
                float iw = fmaxf(bw, 0.0f), ih = fmaxf(bh, 0.0f);
                float inter = __fmul_rn(iw, ih);
                if (inter > 0.0f) {
                    float areaa = area_fn(o.x, o.y, o.z, o.w);
                    float denom = __fsub_rn(__fadd_rn(areaa, areag), inter);
                    gm = fmaxf(gm, __fdiv_rn(inter, denom));
                }
            }
        }
        g_gtmaxf[ka] = gm;
    }
    const int W = sdim[1], KA = sdim[2];
    const int HW = sdim[0] * W;
    if (ka >= KA) return;
    int a = ka % A_NUM;
    int cell = ka / A_NUM;
    int x = cell % W, y = cell / W;
    int rank = 0;
#pragma unroll
    for (int a2 = 0; a2 < A_NUM; a2++) {
        int4 bb = sb[a2];
        int nx = bb.y - bb.x + 1; if (nx < 0) nx = 0;
        int rb = min(bb.w, y - 1) - bb.z + 1; if (rb < 0) rb = 0;
        rank += rb * nx;
        if (y >= bb.z && y <= bb.w) {
            int xb = min(bb.y, x - 1) - bb.x + 1; if (xb < 0) xb = 0;
            rank += xb;
            if (a2 < a && x >= bb.x && x <= bb.y) rank += 1;
        }
    }
    int4 mb = sb[a];
    bool inside = (x >= mb.x && x <= mb.y && y >= mb.z && y <= mb.w);
    if (inside) {
        float sx = __fmul_rn(16.0f, (float)x), sy = __fmul_rn(16.0f, (float)y);
        float4 o = sbx[a];
        g_anc4[rank] = make_float4(__fadd_rn(sx, o.x), __fadd_rn(sy, o.y),
                                   __fadd_rn(sx, o.z), __fadd_rn(sy, o.w));
        g_rank_t[a * HW + cell] = rank;
    } else {
        g_rank_t[a * HW + cell] = -1;
    }
}

// ------ K2: fused pass: best/arg + hit + labels + priority + histogram -------
__global__ void k_passA(const float* __restrict__ gt) {
    int b = blockIdx.y;
    if (b >= g_p.B) return;
    const int N = g_p.N, G = g_p.G;
    int base = blockIdx.x * (256 * APT);
    if (base >= N) return;
    __shared__ float4 sgt[G_MAX];
    __shared__ float sga[G_MAX], sgm[G_MAX];
    __shared__ float4 cgt[G_MAX];
    __shared__ float cga[G_MAX], cgm[G_MAX];
    __shared__ unsigned char cgi[G_MAX];
    __shared__ int shf[256], shb[256];
    __shared__ int s_ymin, s_ymax, s_scnt;
    __shared__ unsigned s_bal[2];
    int tid = threadIdx.x;
    int lane = tid & 31;
    shf[tid] = 0; shb[tid] = 0;
    if (tid == 0) { s_ymin = 0x7f7fffff; s_ymax = 0; }
    if (tid < G_MAX) {
        float4 gb;
        float gm = 0.0f;
        if (tid < G) {
            gb = reinterpret_cast<const float4*>(gt)[(size_t)b * G + tid];
            gm = g_gtmaxf[b * G_MAX + tid];
        } else {
            gb = make_float4(2e9f, 2e9f, -2e9f, -2e9f);
        }
        sgt[tid] = gb;
        sga[tid] = area_fn(gb.x, gb.y, gb.z, gb.w);
        sgm[tid] = gm;
    }
    __syncthreads();
    float4 A[APT]; float area[APT]; float best[APT]; int jarg[APT]; bool hit[APT]; bool val[APT];
    float ymn = 3e9f, ymx = -3e9f;
#pragma unroll
    for (int k = 0; k < APT; k++) {
        int idx = base + k * 256 + tid;
        val[k] = idx < N;
        A[k] = val[k] ? g_anc4[idx] : make_float4(3e9f, 3e9f, -3e9f, -3e9f);
        area[k] = area_fn(A[k].x, A[k].y, A[k].z, A[k].w);
        best[k] = 0.0f; jarg[k] = -1; hit[k] = false;
        ymn = fminf(ymn, A[k].y);
        ymx = fmaxf(ymx, A[k].w);
    }
#pragma unroll
    for (int off = 16; off > 0; off >>= 1) {
        ymn = fminf(ymn, __shfl_xor_sync(0xFFFFFFFFu, ymn, off));
        ymx = fmaxf(ymx, __shfl_xor_sync(0xFFFFFFFFu, ymx, off));
    }
    if (lane == 0) {
        atomicMin(&s_ymin, __float_as_int(ymn));
        atomicMax(&s_ymax, __float_as_int(ymx));
    }
    __syncthreads();
    float wlo = __int_as_float(s_ymin) - 4.0f;
    float whi = __int_as_float(s_ymax) + 4.0f;
    // order-preserving cull+compact of gts overlapping this block's y-strip
    bool pass = false;
    unsigned bal = 0;
    if (tid < 64) {
        if (tid < G) {
            float4 gb = sgt[tid];
            pass = (gb.w >= wlo) && (gb.y <= whi);
        }
        bal = __ballot_sync(0xFFFFFFFFu, pass);
        if (lane == 0) s_bal[tid >> 5] = bal;
    }
    __syncthreads();
    if (tid < 64 && pass) {
        int w = tid >> 5;
        int off = __popc(bal & ((1u << lane) - 1u)) + (w ? __popc(s_bal[0]) : 0);
        cgt[off] = sgt[tid]; cga[off] = sga[tid]; cgm[off] = sgm[tid];
        cgi[off] = (unsigned char)tid;
    }
    if (tid == 0) s_scnt = __popc(s_bal[0]) + __popc(s_bal[1]);
    __syncthreads();
    int scnt = s_scnt;
    for (int j = 0; j < scnt; j++) {
        float4 gb = cgt[j]; float ag = cga[j]; float gm = cgm[j];
#pragma unroll
        for (int k = 0; k < APT; k++) {
            float iw = __fadd_rn(__fsub_rn(fminf(A[k].z, gb.z), fmaxf(A[k].x, gb.x)), 1.0f);
            float ih = __fadd_rn(__fsub_rn(fminf(A[k].w, gb.w), fmaxf(A[k].y, gb.y)), 1.0f);
            iw = fmaxf(iw, 0.0f);
            ih = fmaxf(ih, 0.0f);
            float inter = __fmul_rn(iw, ih);
            if (inter > 0.0f) {   // iou == +0 exactly when inter == 0
                float denom = __fsub_rn(__fadd_rn(area[k], ag), inter);
                float iou = __fdiv_rn(inter, denom);
                hit[k] |= (iou == gm);
                if (iou > best[k]) { best[k] = iou; jarg[k] = j; }
            }
        }
    }
    // epilogue: final labels + threefry priority + shared histogram
    uint32_t kf0 = g_keyf[b * 2], kf1 = g_keyf[b * 2 + 1];
    uint32_t kb0 = g_keyb[b * 2], kb1 = g_keyb[b * 2 + 1];
#pragma unroll
    for (int k = 0; k < APT; k++) {
        if (val[k]) {
            int idx = base + k * 256 + tid;
            int lab = -1;
            if (best[k] < 0.3f) lab = 0;
            if (best[k] >= 0.7f) lab = 1;
            if (hit[k]) lab = 1;
            g_arg[(size_t)b * N_MAX + idx] =
                (jarg[k] < 0) ? (unsigned char)0 : cgi[jarg[k]];
            uint32_t word = 0u;
            if (lab >= 0) {
                uint32_t q0 = (lab == 1) ? kf0 : kb0;
                uint32_t q1 = (lab == 1) ? kf1 : kb1;
                uint32_t c0 = 0u, c1 = (uint32_t)idx;
                tf2x32(q0, q1, c0, c1);
                uint32_t p = (c0 ^ c1) >> 9;
                word = (p << 2) | (uint32_t)(lab + 1);
                atomicAdd((lab == 1) ? &shf[p >> 15] : &shb[p >> 15], 1);
            }
            g_lp[(size_t)b * N_MAX + idx] = word;
        }
    }
    __syncthreads();
    int cf = shf[tid], cb = shb[tid];
    if (cf) atomicAdd(&g_hist[b][0][tid], cf);
    if (cb) atomicAdd(&g_hist[b][1][tid], cb);
}

// ------ K3: fused subsample: scans -> gather -> exact k-th -> thresholds -----
__global__ void k_select() {
    int b = blockIdx.x;
    if (b >= g_p.B) return;
    int tid = threadIdx.x, lane = tid & 31, w = tid >> 5;
    __shared__ int s_ws[8], s_ws2[8];
    __shared__ int s_inf[8];  // 1 df, 2 lkf, 3 needf, 5 db, 6 lkb, 7 needb
    __shared__ unsigned long long sf[SELB], sbb[SELB];
    __shared__ int s_cf, s_cb;
    if (tid == 0) { s_cf = 0; s_cb = 0; s_inf[3] = 0; s_inf[7] = 0; }
    int cf = 0, cumf = 0, cb2 = 0, cumb = 0;
    if (tid < 256) {
        cf = g_hist[b][0][tid];
        cb2 = g_hist[b][1][tid];
        int v = cf;
#pragma unroll
        for (int o = 1; o < 32; o <<= 1) {
            int u = __shfl_up_sync(0xFFFFFFFFu, v, o);
            if (lane >= o) v += u;
        }
        if (lane == 31) s_ws[w] = v;
        cumf = v;
        v = cb2;
#pragma unroll
        for (int o = 1; o < 32; o <<= 1) {
            int u = __shfl_up_sync(0xFFFFFFFFu, v, o);
            if (lane >= o) v += u;
        }
        if (lane == 31) s_ws2[w] = v;
        cumb = v;
    }
    __syncthreads();
    if (tid == 0) {
        int acc = 0;
        for (int i = 0; i < 8; i++) { acc += s_ws[i]; s_ws[i] = acc; }
        acc = 0;
        for (int i = 0; i < 8; i++) { acc += s_ws2[i]; s_ws2[i] = acc; }
    }
    __syncthreads();
    int fgtot = s_ws[7];
    int bgtot = s_ws2[7];
    int numbg = 256 - min(fgtot, 128);
    if (tid < 256) {
        if (w > 0) { cumf += s_ws[w - 1]; cumb += s_ws2[w - 1]; }
        if (fgtot > 128 && cumf >= 128 && cumf - cf < 128) {
            s_inf[1] = tid; s_inf[2] = 128 - (cumf - cf); s_inf[3] = 1;
        }
        if (bgtot > numbg && cumb >= numbg && cumb - cb2 < numbg) {
            s_inf[5] = tid; s_inf[6] = numbg - (cumb - cb2); s_inf[7] = 1;
        }
    }
    __syncthreads();
    int needf = s_inf[3], df = s_inf[1], lkf = s_inf[2];
    int needb = s_inf[7], db = s_inf[5], lkb = s_inf[6];
    if (tid == 0) {
        if (!needf) g_thr[b][0] = ~0ull;
        if (!needb) g_thr[b][1] = ~0ull;
    }
    if (needf || needb) {
        const int N = g_p.N;
        const uint32_t* lp = g_lp + (size_t)b * N_MAX;
        for (int i = tid; i < N; i += 1024) {
            uint32_t wd = lp[i];
            if (!wd) continue;
            int bin = (wd >> 17) & 0xFF;
            if ((wd & 3u) == 2u) {
                if (needf && bin == df) {
                    int pos = atomicAdd(&s_cf, 1);
                    if (pos < SELB)
                        sf[pos] = ((unsigned long long)(wd >> 2) << 16) | (unsigned)i;
                }
            } else {
                if (needb && bin == db) {
                    int pos = atomicAdd(&s_cb, 1);
                    if (pos < SELB)
                        sbb[pos] = ((unsigned long long)(wd >> 2) << 16) | (unsigned)i;
                }
            }
        }
        __syncthreads();
        int mf = min(s_cf, SELB), mb = min(s_cb, SELB);
        if (needf && tid < mf) {
            unsigned long long key = sf[tid];
            int c = 0;
            for (int j = 0; j < mf; j++) c += (sf[j] < key);
            if (c == lkf - 1) g_thr[b][0] = key;
        }
        if (needb && tid < mb) {
            unsigned long long key = sbb[tid];
            int c = 0;
            for (int j = 0; j < mb; j++) c += (sbb[j] < key);
            if (c == lkb - 1) g_thr[b][1] = key;
        }
    }
}

// ------ K4: emit labels [B,9,H,W]; sparse reg scatter for kept fg ------------
__global__ void k_emit(const float* __restrict__ gt, float* __restrict__ out) {
    int b = blockIdx.y;
    if (b >= g_p.B) return;
    const int H = g_p.H, W = g_p.W, HW = H * W, KA = g_p.KA, G = g_p.G, B = g_p.B;
    int t = blockIdx.x * blockDim.x + threadIdx.x;
    if (t >= KA) return;
    int rank = g_rank_t[t];
    int l = -1;
    uint32_t wd = 0;
    if (rank >= 0) {
        wd = g_lp[(size_t)b * N_MAX + rank];
        l = (int)(wd & 3u) - 1;
        if (l >= 0) {
            unsigned long long key =
                ((unsigned long long)(wd >> 2) << 16) | (unsigned)rank;
            if (key > g_thr[b][l == 1 ? 0 : 1]) l = -1;
        }
    }
    out[(size_t)b * A_NUM * HW + t] = (float)l;
    if (l == 1) {  // rare: <=128 threads per image take this path
        int a = t / HW;
        int rem = t - a * HW;
        int arg = g_arg[(size_t)b * N_MAX + rank];
        float4 av = g_anc4[rank];
        const float* gp = gt + ((size_t)b * G + arg) * 4;
        float g0 = gp[0], g1 = gp[1], g2 = gp[2], g3 = gp[3];
        float aw = av.z - av.x + 1.0f, ah = av.w - av.y + 1.0f;
        float acx = av.x + 0.5f * (aw - 1.0f), acy = av.y + 0.5f * (ah - 1.0f);
        float gw = g2 - g0 + 1.0f, gh = g3 - g1 + 1.0f;
        float gcx = g0 + 0.5f * (gw - 1.0f), gcy = g1 + 0.5f * (gh - 1.0f);
        float* out_reg = out + (size_t)B * A_NUM * HW;
        size_t rb = ((size_t)b * A_NUM * 4 + (size_t)a * 4) * HW + rem;
        out_reg[rb]                  = (gcx - acx) / aw;
        out_reg[rb + HW]             = (gcy - acy) / ah;
        out_reg[rb + 2 * (size_t)HW] = logf(gw / aw);
        out_reg[rb + 3 * (size_t)HW] = logf(gh / ah);
    }
}

extern "C" void kernel_launch(void* const* d_in, const int* in_sizes, int n_in,
                              void* d_out, int out_size) {
    const float* gt = (const float*)d_in[0];
    const int* pB = (const int*)d_in[1];
    const int* pG = (const int*)d_in[2];
    const int* pH = (const int*)d_in[3];
    const int* pW = (const int*)d_in[4];

    // reg region = last 4/5 of out (out = [B*9*HW labels][B*36*HW reg])
    int lab_elems = out_size / 5;
    int reg_elems = out_size - lab_elems;
    int n4 = reg_elems / 4;  // float4 count (reg_elems divisible by 4)
    k_zero<<<(n4 + 255) / 256, 256>>>((float4*)((float*)d_out + lab_elems), n4);
    k_grid<<<(KA_MAX + 255) / 256, 256>>>(gt, pB, pG, pH, pW);
    {
        dim3 g((N_MAX + 256 * APT - 1) / (256 * APT), B_MAX);
        k_passA<<<g, 256>>>(gt);
    }
    k_select<<<B_MAX, 1024>>>();
    {
        dim3 g((KA_MAX + 255) / 256, B_MAX);
        k_emit<<<g, 256>>>(gt, (float*)d_out);
    }
}

// round 12
// speedup vs baseline: 1.0582x; 1.0582x over previous
#include <cuda_runtime.h>
#include <cstdint>
#include <math_constants.h>

#define A_NUM 9
#define KA_MAX 36864   // 64*64*9
#define N_MAX  36864
#define B_MAX  32
#define G_MAX  64
#define SELB   512
#define APT    4
#define FGB    1024
#define BGB    2048

struct Params { int B, G, H, W, KA, N; };
__device__ Params g_p;
__device__ int    g_rank_t[KA_MAX];          // [a][cell] inside rank or -1
__device__ float4 g_anc4[N_MAX];             // inside anchor boxes
__device__ float4 g_abox[A_NUM];
__device__ int4   g_bnd[A_NUM];              // {Lx,Rx,Ly,Ry}
__device__ uint32_t g_keyf[B_MAX * 2];
__device__ uint32_t g_keyb[B_MAX * 2];
__device__ float  g_gtmaxf[B_MAX * G_MAX];   // analytic per-gt max IoU
__device__ unsigned char g_arg[B_MAX * N_MAX];
__device__ uint32_t g_lp[B_MAX * N_MAX];     // (prio<<2) | (lab+1); 0 == lab -1
__device__ int    g_hist[B_MAX][2][256];
__device__ unsigned long long g_thr[B_MAX][2];
__device__ unsigned long long g_fgbuf[B_MAX][FGB];
__device__ unsigned long long g_bgbuf[B_MAX][BGB];
__device__ int    g_fgcnt[B_MAX];
__device__ int    g_bgcnt[B_MAX];

// ---------------- Threefry-2x32 (JAX schedule) -------------------------------
__device__ __forceinline__ uint32_t rotl32(uint32_t x, uint32_t r) {
    return __funnelshift_l(x, x, r);
}
__device__ __forceinline__ void tf2x32(uint32_t k0, uint32_t k1,
                                       uint32_t& x0, uint32_t& x1) {
    uint32_t ks2 = k0 ^ k1 ^ 0x1BD11BDAu;
    x0 += k0; x1 += k1;
    const uint32_t rA[4] = {13u, 15u, 26u, 6u};
    const uint32_t rB[4] = {17u, 29u, 16u, 24u};
#pragma unroll
    for (int i = 0; i < 4; i++) { x0 += x1; x1 = rotl32(x1, rA[i]); x1 ^= x0; }
    x0 += k1; x1 += ks2 + 1u;
#pragma unroll
    for (int i = 0; i < 4; i++) { x0 += x1; x1 = rotl32(x1, rB[i]); x1 ^= x0; }
    x0 += ks2; x1 += k0 + 2u;
#pragma unroll
    for (int i = 0; i < 4; i++) { x0 += x1; x1 = rotl32(x1, rA[i]); x1 ^= x0; }
    x0 += k0; x1 += k1 + 3u;
#pragma unroll
    for (int i = 0; i < 4; i++) { x0 += x1; x1 = rotl32(x1, rB[i]); x1 ^= x0; }
    x0 += k1; x1 += ks2 + 4u;
#pragma unroll
    for (int i = 0; i < 4; i++) { x0 += x1; x1 = rotl32(x1, rA[i]); x1 ^= x0; }
    x0 += ks2; x1 += k0 + 5u;
}

// ---------------- IoU helpers (identical op order; no FMA contraction) -------
__device__ __forceinline__ float area_fn(float x1, float y1, float x2, float y2) {
    return __fmul_rn(__fadd_rn(__fsub_rn(x2, x1), 1.0f),
                     __fadd_rn(__fsub_rn(y2, y1), 1.0f));
}

__device__ __forceinline__ float axis_best(float glo, float ghi,
                                           float olo, float ohi, int L, int R) {
    float t1 = __fmul_rn(__fsub_rn(glo, olo), 0.0625f);
    float t2 = __fmul_rn(__fsub_rn(ghi, ohi), 0.0625f);
    int f1 = (int)floorf(t1), f2 = (int)floorf(t2);
    int cand[6] = {f1 - 1, f1, f1 + 1, f2 - 1, f2, f2 + 1};
    float best = -1e30f;
#pragma unroll
    for (int i = 0; i < 6; i++) {
        int x = min(max(cand[i], L), R);
        float sx = __fmul_rn(16.0f, (float)x);
        float alo = __fadd_rn(sx, olo), ahi = __fadd_rn(sx, ohi);
        float iw = __fadd_rn(__fsub_rn(fminf(ahi, ghi), fmaxf(alo, glo)), 1.0f);
        best = fmaxf(best, iw);
    }
    return best;
}

__device__ __forceinline__ void compute_anchors(int H, int W,
                                                float4* sbx, int4* sb, int* Ntot) {
    const double ratios[3] = {0.5, 1.0, 2.0};
    const double scales[3] = {8.0, 16.0, 32.0};
    int nt = 0;
    for (int r = 0; r < 3; r++) {
        double ws = rint(sqrt(256.0 / ratios[r]));
        double hs = rint(ws * ratios[r]);
        for (int s = 0; s < 3; s++) {
            double Wd = ws * scales[s], Hd = hs * scales[s];
            int a = r * 3 + s;
            double x1 = 7.5 - 0.5 * (Wd - 1.0);
            double y1 = 7.5 - 0.5 * (Hd - 1.0);
            double x2 = 7.5 + 0.5 * (Wd - 1.0);
            double y2 = 7.5 + 0.5 * (Hd - 1.0);
            sbx[a] = make_float4((float)x1, (float)y1, (float)x2, (float)y2);
            int ix1 = (int)llrint(x1), iy1 = (int)llrint(y1);
            int ix2 = (int)llrint(x2), iy2 = (int)llrint(y2);
            int Lx = (ix1 < 0) ? ((-ix1 + 15) / 16) : 0;
            int Ly = (iy1 < 0) ? ((-iy1 + 15) / 16) : 0;
            int nxw = 16 * W - 1 - ix2;
            int nyh = 16 * H - 1 - iy2;
            int Rx = (nxw < 0) ? -1 : min(W - 1, nxw / 16);
            int Ry = (nyh < 0) ? -1 : min(H - 1, nyh / 16);
            sb[a] = make_int4(Lx, Rx, Ly, Ry);
            int nx = Rx - Lx + 1; if (nx < 0) nx = 0;
            int ny = Ry - Ly + 1; if (ny < 0) ny = 0;
            nt += nx * ny;
        }
    }
    *Ntot = nt;
}

// ------ K0: zero the reg region of out (last 4/5 of the buffer) --------------
__global__ void k_zero(float4* reg4, int n4) {
    int i = blockIdx.x * blockDim.x + threadIdx.x;
    if (i < n4) reg4[i] = make_float4(0.f, 0.f, 0.f, 0.f);
}

// ------ K1: setup + rank + anchor compaction + analytic gt_max + zeroing -----
__global__ void k_grid(const float* __restrict__ gt,
                       const int* pB, const int* pG, const int* pH, const int* pW) {
    __shared__ int4 sb[A_NUM];
    __shared__ float4 sbx[A_NUM];
    __shared__ int sdim[5];  // H, W, KA, B, G
    int tid = threadIdx.x;
    if (tid == 0) {
        int H = *pH, W = *pW;
        int Ntot;
        compute_anchors(H, W, sbx, sb, &Ntot);
        int KA = H * W * A_NUM;
        if (KA > KA_MAX) KA = KA_MAX;
        int B = *pB, G = *pG;
        if (B > B_MAX) B = B_MAX;
        if (G > G_MAX) G = G_MAX;
        sdim[0] = H; sdim[1] = W; sdim[2] = KA; sdim[3] = B; sdim[4] = G;
        if (blockIdx.x == 0) {
            Params p; p.B = B; p.G = G; p.H = H; p.W = W; p.KA = KA; p.N = Ntot;
            g_p = p;
            for (int a = 0; a < A_NUM; a++) { g_abox[a] = sbx[a]; g_bnd[a] = sb[a]; }
        }
    }
    __syncthreads();
    int ka = blockIdx.x * blockDim.x + tid;
    if (blockIdx.x == 0 && tid < B_MAX) {
        uint32_t h0 = 0u, h1 = (uint32_t)tid;
        tf2x32(0u, 42u, h0, h1);
        uint32_t f0 = 0u, f1 = 0u; tf2x32(h0, h1, f0, f1);
        uint32_t c0 = 0u, c1 = 1u; tf2x32(h0, h1, c0, c1);
        g_keyf[tid * 2 + 0] = f0; g_keyf[tid * 2 + 1] = f1;
        g_keyb[tid * 2 + 0] = c0; g_keyb[tid * 2 + 1] = c1;
    }
    if (ka < B_MAX * 2 * 256) ((int*)g_hist)[ka] = 0;
    if (ka < B_MAX) { g_fgcnt[ka] = 0; g_bgcnt[ka] = 0; }
    const int B = sdim[3], G = sdim[4];
    // analytic per-gt max IoU
    if (ka < B_MAX * G_MAX) {
        int b = ka >> 6, g = ka & 63;
        float gm = 0.0f;
        if (b < B && g < G) {
            float4 gb = reinterpret_cast<const float4*>(gt)[(size_t)b * G + g];
            float areag = area_fn(gb.x, gb.y, gb.z, gb.w);
            for (int a = 0; a < A_NUM; a++) {
                int4 bb = sb[a];
                if (bb.y < bb.x || bb.w < bb.z) continue;
                float4 o = sbx[a];
                float bw = axis_best(gb.x, gb.z, o.x, o.z, bb.x, bb.y);
                float bh = axis_best(gb.y, gb.w, o.y, o.w, bb.z, bb.w);
                float iw = fmaxf(bw, 0.0f), ih = fmaxf(bh, 0.0f);
                float inter = __fmul_rn(iw, ih);
                if (inter > 0.0f) {
                    float areaa = area_fn(o.x, o.y, o.z, o.w);
                    float denom = __fsub_rn(__fadd_rn(areaa, areag), inter);
                    gm = fmaxf(gm, __fdiv_rn(inter, denom));
                }
            }
        }
        g_gtmaxf[ka] = gm;
    }
    const int W = sdim[1], KA = sdim[2];
    const int HW = sdim[0] * W;
    if (ka >= KA) return;
    int a = ka % A_NUM;
    int cell = ka / A_NUM;
    int x = cell % W, y = cell / W;
    int rank = 0;
#pragma unroll
    for (int a2 = 0; a2 < A_NUM; a2++) {
        int4 bb = sb[a2];
        int nx = bb.y - bb.x + 1; if (nx < 0) nx = 0;
        int rb = min(bb.w, y - 1) - bb.z + 1; if (rb < 0) rb = 0;
        rank += rb * nx;
        if (y >= bb.z && y <= bb.w) {
            int xb = min(bb.y, x - 1) - bb.x + 1; if (xb < 0) xb = 0;
            rank += xb;
            if (a2 < a && x >= bb.x && x <= bb.y) rank += 1;
        }
    }
    int4 mb = sb[a];
    bool inside = (x >= mb.x && x <= mb.y && y >= mb.z && y <= mb.w);
    if (inside) {
        float sx = __fmul_rn(16.0f, (float)x), sy = __fmul_rn(16.0f, (float)y);
        float4 o = sbx[a];
        g_anc4[rank] = make_float4(__fadd_rn(sx, o.x), __fadd_rn(sy, o.y),
                                   __fadd_rn(sx, o.z), __fadd_rn(sy, o.w));
        g_rank_t[a * HW + cell] = rank;
    } else {
        g_rank_t[a * HW + cell] = -1;
    }
}

// ------ K2: fused pass: best/arg + hit + labels + prio + hist + pre-gather ---
__global__ void k_passA(const float* __restrict__ gt) {
    int b = blockIdx.y;
    if (b >= g_p.B) return;
    const int N = g_p.N, G = g_p.G;
    int base = blockIdx.x * (256 * APT);
    if (base >= N) return;
    __shared__ float4 sgt[G_MAX];
    __shared__ float sga[G_MAX], sgm[G_MAX];
    __shared__ float4 cgt[G_MAX];
    __shared__ float cga[G_MAX], cgm[G_MAX];
    __shared__ unsigned char cgi[G_MAX];
    __shared__ int shf[256], shb[256];
    __shared__ int s_ymin, s_ymax, s_scnt;
    __shared__ unsigned s_bal[2];
    int tid = threadIdx.x;
    int lane = tid & 31;
    shf[tid] = 0; shb[tid] = 0;
    if (tid == 0) { s_ymin = 0x7f7fffff; s_ymax = 0; }
    if (tid < G_MAX) {
        float4 gb;
        float gm = 0.0f;
        if (tid < G) {
            gb = reinterpret_cast<const float4*>(gt)[(size_t)b * G + tid];
            gm = g_gtmaxf[b * G_MAX + tid];
        } else {
            gb = make_float4(2e9f, 2e9f, -2e9f, -2e9f);
        }
        sgt[tid] = gb;
        sga[tid] = area_fn(gb.x, gb.y, gb.z, gb.w);
        sgm[tid] = gm;
    }
    __syncthreads();
    float4 A[APT]; float area[APT]; float best[APT]; int jarg[APT]; bool hit[APT]; bool val[APT];
    float ymn = 3e9f, ymx = -3e9f;
#pragma unroll
    for (int k = 0; k < APT; k++) {
        int idx = base + k * 256 + tid;
        val[k] = idx < N;
        A[k] = val[k] ? g_anc4[idx] : make_float4(3e9f, 3e9f, -3e9f, -3e9f);
        area[k] = area_fn(A[k].x, A[k].y, A[k].z, A[k].w);
        best[k] = 0.0f; jarg[k] = -1; hit[k] = false;
        ymn = fminf(ymn, A[k].y);
        ymx = fmaxf(ymx, A[k].w);
    }
#pragma unroll
    for (int off = 16; off > 0; off >>= 1) {
        ymn = fminf(ymn, __shfl_xor_sync(0xFFFFFFFFu, ymn, off));
        ymx = fmaxf(ymx, __shfl_xor_sync(0xFFFFFFFFu, ymx, off));
    }
    if (lane == 0) {
        atomicMin(&s_ymin, __float_as_int(ymn));
        atomicMax(&s_ymax, __float_as_int(ymx));
    }
    __syncthreads();
    float wlo = __int_as_float(s_ymin) - 4.0f;
    float whi = __int_as_float(s_ymax) + 4.0f;
    bool pass = false;
    unsigned bal = 0;
    if (tid < 64) {
        if (tid < G) {
            float4 gb = sgt[tid];
            pass = (gb.w >= wlo) && (gb.y <= whi);
        }
        bal = __ballot_sync(0xFFFFFFFFu, pass);
        if (lane == 0) s_bal[tid >> 5] = bal;
    }
    __syncthreads();
    if (tid < 64 && pass) {
        int w = tid >> 5;
        int off = __popc(bal & ((1u << lane) - 1u)) + (w ? __popc(s_bal[0]) : 0);
        cgt[off] = sgt[tid]; cga[off] = sga[tid]; cgm[off] = sgm[tid];
        cgi[off] = (unsigned char)tid;
    }
    if (tid == 0) s_scnt = __popc(s_bal[0]) + __popc(s_bal[1]);
    __syncthreads();
    int scnt = s_scnt;
    for (int j = 0; j < scnt; j++) {
        float4 gb = cgt[j]; float ag = cga[j]; float gm = cgm[j];
#pragma unroll
        for (int k = 0; k < APT; k++) {
            float iw = __fadd_rn(__fsub_rn(fminf(A[k].z, gb.z), fmaxf(A[k].x, gb.x)), 1.0f);
            float ih = __fadd_rn(__fsub_rn(fminf(A[k].w, gb.w), fmaxf(A[k].y, gb.y)), 1.0f);
            iw = fmaxf(iw, 0.0f);
            ih = fmaxf(ih, 0.0f);
            float inter = __fmul_rn(iw, ih);
            if (inter > 0.0f) {   // iou == +0 exactly when inter == 0
                float denom = __fsub_rn(__fadd_rn(area[k], ag), inter);
                float iou = __fdiv_rn(inter, denom);
                hit[k] |= (iou == gm);
                if (iou > best[k]) { best[k] = iou; jarg[k] = j; }
            }
        }
    }
    // epilogue: labels + threefry priority + histogram + candidate pre-gather
    uint32_t kf0 = g_keyf[b * 2], kf1 = g_keyf[b * 2 + 1];
    uint32_t kb0 = g_keyb[b * 2], kb1 = g_keyb[b * 2 + 1];
#pragma unroll
    for (int k = 0; k < APT; k++) {
        if (val[k]) {
            int idx = base + k * 256 + tid;
            int lab = -1;
            if (best[k] < 0.3f) lab = 0;
            if (best[k] >= 0.7f) lab = 1;
            if (hit[k]) lab = 1;
            g_arg[(size_t)b * N_MAX + idx] =
                (jarg[k] < 0) ? (unsigned char)0 : cgi[jarg[k]];
            uint32_t word = 0u;
            if (lab >= 0) {
                uint32_t q0 = (lab == 1) ? kf0 : kb0;
                uint32_t q1 = (lab == 1) ? kf1 : kb1;
                uint32_t c0 = 0u, c1 = (uint32_t)idx;
                tf2x32(q0, q1, c0, c1);
                uint32_t p = (c0 ^ c1) >> 9;
                word = (p << 2) | (uint32_t)(lab + 1);
                atomicAdd((lab == 1) ? &shf[p >> 15] : &shb[p >> 15], 1);
                unsigned long long key =
                    ((unsigned long long)p << 16) | (unsigned)idx;
                if (lab == 1) {
                    int pos = atomicAdd(&g_fgcnt[b], 1);
                    if (pos < FGB) g_fgbuf[b][pos] = key;
                } else if ((p >> 15) < 8u) {
                    int pos = atomicAdd(&g_bgcnt[b], 1);
                    if (pos < BGB) g_bgbuf[b][pos] = key;
                }
            }
            g_lp[(size_t)b * N_MAX + idx] = word;
        }
    }
    __syncthreads();
    int cf = shf[tid], cb = shb[tid];
    if (cf) atomicAdd(&g_hist[b][0][tid], cf);
    if (cb) atomicAdd(&g_hist[b][1][tid], cb);
}

// ------ K3: subsample thresholds from pre-gathered candidates ----------------
__global__ void k_select() {
    int b = blockIdx.x;
    if (b >= g_p.B) return;
    int tid = threadIdx.x, lane = tid & 31, w = tid >> 5;  // 256 threads
    __shared__ int s_ws[8], s_ws2[8];
    __shared__ int s_inf[8];  // 1 df, 2 lkf, 3 needf, 5 db, 6 lkb, 7 needb
    __shared__ unsigned long long cand[SELB];
    __shared__ int s_c;
    if (tid == 0) { s_inf[3] = 0; s_inf[7] = 0; }
    int cf = g_hist[b][0][tid];
    int cb2 = g_hist[b][1][tid];
    int v = cf;
#pragma unroll
    for (int o = 1; o < 32; o <<= 1) {
        int u = __shfl_up_sync(0xFFFFFFFFu, v, o);
        if (lane >= o) v += u;
    }
    if (lane == 31) s_ws[w] = v;
    int cumf = v;
    v = cb2;
#pragma unroll
    for (int o = 1; o < 32; o <<= 1) {
        int u = __shfl_up_sync(0xFFFFFFFFu, v, o);
        if (lane >= o) v += u;
    }
    if (lane == 31) s_ws2[w] = v;
    int cumb = v;
    __syncthreads();
    if (tid == 0) {
        int acc = 0;
        for (int i = 0; i < 8; i++) { acc += s_ws[i]; s_ws[i] = acc; }
        acc = 0;
        for (int i = 0; i < 8; i++) { acc += s_ws2[i]; s_ws2[i] = acc; }
    }
    __syncthreads();
    int fgtot = s_ws[7];
    int bgtot = s_ws2[7];
    int numbg = 256 - min(fgtot, 128);
    if (w > 0) { cumf += s_ws[w - 1]; cumb += s_ws2[w - 1]; }
    if (fgtot > 128 && cumf >= 128 && cumf - cf < 128) {
        s_inf[1] = tid; s_inf[2] = 128 - (cumf - cf); s_inf[3] = 1;
    }
    if (bgtot > numbg && cumb >= numbg && cumb - cb2 < numbg) {
        s_inf[5] = tid; s_inf[6] = numbg - (cumb - cb2); s_inf[7] = 1;
    }
    __syncthreads();
    int needf = s_inf[3], df = s_inf[1], lkf = s_inf[2];
    int needb = s_inf[7], db = s_inf[5], lkb = s_inf[6];
    if (tid == 0) {
        if (!needf) g_thr[b][0] = ~0ull;
        if (!needb) g_thr[b][1] = ~0ull;
    }
    const int N = g_p.N;
    const uint32_t* lp = g_lp + (size_t)b * N_MAX;
    // ---- fg threshold ----
    if (needf) {
        if (tid == 0) s_c = 0;
        __syncthreads();
        int cnt = g_fgcnt[b];
        if (cnt <= FGB) {
            for (int i = tid; i < cnt; i += 256) {
                unsigned long long key = g_fgbuf[b][i];
                if ((int)((key >> 31) & 0xFF) == df) {
                    int pos = atomicAdd(&s_c, 1);
                    if (pos < SELB) cand[pos] = key;
                }
            }
        } else {  // fallback: full scan (not expected)
            for (int i = tid; i < N; i += 256) {
                uint32_t wd = lp[i];
                if ((wd & 3u) == 2u && (int)((wd >> 17) & 0xFF) == df) {
                    int pos = atomicAdd(&s_c, 1);
                    if (pos < SELB)
                        cand[pos] = ((unsigned long long)(wd >> 2) << 16) | (unsigned)i;
                }
            }
        }
        __syncthreads();
        int m = min(s_c, SELB);
        for (int i = tid; i < m; i += 256) {
            unsigned long long key = cand[i];
            int c = 0;
            for (int j = 0; j < m; j++) c += (cand[j] < key);
            if (c == lkf - 1) g_thr[b][0] = key;
        }
        __syncthreads();
    }
    // ---- bg threshold ----
    if (needb) {
        if (tid == 0) s_c = 0;
        __syncthreads();
        int cnt = g_bgcnt[b];
        if (db < 8 && cnt <= BGB) {
            for (int i = tid; i < cnt; i += 256) {
                unsigned long long key = g_bgbuf[b][i];
                if ((int)((key >> 31) & 0xFF) == db) {
                    int pos = atomicAdd(&s_c, 1);
                    if (pos < SELB) cand[pos] = key;
                }
            }
        } else {  // fallback: full scan (not expected)
            for (int i = tid; i < N; i += 256) {
                uint32_t wd = lp[i];
                if ((wd & 3u) == 1u && (int)((wd >> 17) & 0xFF) == db) {
                    int pos = atomicAdd(&s_c, 1);
                    if (pos < SELB)
                        cand[pos] = ((unsigned long long)(wd >> 2) << 16) | (unsigned)i;
                }
            }
        }
        __syncthreads();
        int m = min(s_c, SELB);
        for (int i = tid; i < m; i += 256) {
            unsigned long long key = cand[i];
            int c = 0;
            for (int j = 0; j < m; j++) c += (cand[j] < key);
            if (c == lkb - 1) g_thr[b][1] = key;
        }
    }
}

// ------ K4: emit labels [B,9,H,W]; sparse reg scatter for kept fg ------------
__global__ void k_emit(const float* __restrict__ gt, float* __restrict__ out) {
    int b = blockIdx.y;
    if (b >= g_p.B) return;
    const int H = g_p.H, W = g_p.W, HW = H * W, KA = g_p.KA, G = g_p.G, B = g_p.B;
    int t = blockIdx.x * blockDim.x + threadIdx.x;
    if (t >= KA) return;
    int rank = g_rank_t[t];
    int l = -1;
    uint32_t wd = 0;
    if (rank >= 0) {
        wd = g_lp[(size_t)b * N_MAX + rank];
        l = (int)(wd & 3u) - 1;
        if (l >= 0) {
            unsigned long long key =
                ((unsigned long long)(wd >> 2) << 16) | (unsigned)rank;
            if (key > g_thr[b][l == 1 ? 0 : 1]) l = -1;
        }
    }
    out[(size_t)b * A_NUM * HW + t] = (float)l;
    if (l == 1) {  // rare: <=128 threads per image take this path
        int a = t / HW;
        int rem = t - a * HW;
        int arg = g_arg[(size_t)b * N_MAX + rank];
        float4 av = g_anc4[rank];
        const float* gp = gt + ((size_t)b * G + arg) * 4;
        float g0 = gp[0], g1 = gp[1], g2 = gp[2], g3 = gp[3];
        float aw = av.z - av.x + 1.0f, ah = av.w - av.y + 1.0f;
        float acx = av.x + 0.5f * (aw - 1.0f), acy = av.y + 0.5f * (ah - 1.0f);
        float gw = g2 - g0 + 1.0f, gh = g3 - g1 + 1.0f;
        float gcx = g0 + 0.5f * (gw - 1.0f), gcy = g1 + 0.5f * (gh - 1.0f);
        float* out_reg = out + (size_t)B * A_NUM * HW;
        size_t rb = ((size_t)b * A_NUM * 4 + (size_t)a * 4) * HW + rem;
        out_reg[rb]                  = (gcx - acx) / aw;
        out_reg[rb + HW]             = (gcy - acy) / ah;
        out_reg[rb + 2 * (size_t)HW] = logf(gw / aw);
        out_reg[rb + 3 * (size_t)HW] = logf(gh / ah);
    }
}

extern "C" void kernel_launch(void* const* d_in, const int* in_sizes, int n_in,
                              void* d_out, int out_size) {
    const float* gt = (const float*)d_in[0];
    const int* pB = (const int*)d_in[1];
    const int* pG = (const int*)d_in[2];
    const int* pH = (const int*)d_in[3];
    const int* pW = (const int*)d_in[4];

    // reg region = last 4/5 of out (out = [B*9*HW labels][B*36*HW reg])
    int lab_elems = out_size / 5;
    int reg_elems = out_size - lab_elems;
    int n4 = reg_elems / 4;
    k_zero<<<(n4 + 255) / 256, 256>>>((float4*)((float*)d_out + lab_elems), n4);
    k_grid<<<(KA_MAX + 255) / 256, 256>>>(gt, pB, pG, pH, pW);
    {
        dim3 g((N_MAX + 256 * APT - 1) / (256 * APT), B_MAX);
        k_passA<<<g, 256>>>(gt);
    }
    k_select<<<B_MAX, 256>>>();
    {
        dim3 g((KA_MAX + 255) / 256, B_MAX);
        k_emit<<<g, 256>>>(gt, (float*)d_out);
    }
}

// round 13
// speedup vs baseline: 1.0915x; 1.0315x over previous
#include <cuda_runtime.h>
#include <cstdint>
#include <math_constants.h>

#define A_NUM 9
#define KA_MAX 36864   // 64*64*9
#define N_MAX  36864
#define B_MAX  32
#define G_MAX  64
#define SELB   512
#define APT    4
#define FGB    1024
#define BGB    2048

struct Params { int B, G, H, W, KA, N; };
__device__ Params g_p;
__device__ int    g_rank_t[KA_MAX];          // [a][cell] inside rank or -1
__device__ float4 g_anc4[N_MAX];             // inside anchor boxes
__device__ float4 g_abox[A_NUM];
__device__ int4   g_bnd[A_NUM];              // {Lx,Rx,Ly,Ry}
__device__ uint32_t g_keyf[B_MAX * 2];
__device__ uint32_t g_keyb[B_MAX * 2];
__device__ float  g_gtmaxf[B_MAX * G_MAX];   // analytic per-gt max IoU
__device__ unsigned char g_arg[B_MAX * N_MAX];
__device__ uint32_t g_lp[B_MAX * N_MAX];     // (prio<<2) | (lab+1); 0 == lab -1
__device__ unsigned long long g_thr[B_MAX][2];
__device__ unsigned long long g_fgbuf[B_MAX][FGB];
__device__ unsigned long long g_bgbuf[B_MAX][BGB];
__device__ int    g_fgcnt[B_MAX];
__device__ int    g_bgcnt[B_MAX];            // count of bg with bin<8
__device__ int    g_bgtot[B_MAX];            // total bg count

// ---------------- Threefry-2x32 (JAX schedule) -------------------------------
__device__ __forceinline__ uint32_t rotl32(uint32_t x, uint32_t r) {
    return __funnelshift_l(x, x, r);
}
__device__ __forceinline__ void tf2x32(uint32_t k0, uint32_t k1,
                                       uint32_t& x0, uint32_t& x1) {
    uint32_t ks2 = k0 ^ k1 ^ 0x1BD11BDAu;
    x0 += k0; x1 += k1;
    const uint32_t rA[4] = {13u, 15u, 26u, 6u};
    const uint32_t rB[4] = {17u, 29u, 16u, 24u};
#pragma unroll
    for (int i = 0; i < 4; i++) { x0 += x1; x1 = rotl32(x1, rA[i]); x1 ^= x0; }
    x0 += k1; x1 += ks2 + 1u;
#pragma unroll
    for (int i = 0; i < 4; i++) { x0 += x1; x1 = rotl32(x1, rB[i]); x1 ^= x0; }
    x0 += ks2; x1 += k0 + 2u;
#pragma unroll
    for (int i = 0; i < 4; i++) { x0 += x1; x1 = rotl32(x1, rA[i]); x1 ^= x0; }
    x0 += k0; x1 += k1 + 3u;
#pragma unroll
    for (int i = 0; i < 4; i++) { x0 += x1; x1 = rotl32(x1, rB[i]); x1 ^= x0; }
    x0 += k1; x1 += ks2 + 4u;
#pragma unroll
    for (int i = 0; i < 4; i++) { x0 += x1; x1 = rotl32(x1, rA[i]); x1 ^= x0; }
    x0 += ks2; x1 += k0 + 5u;
}

// ---------------- IoU helpers (identical op order; no FMA contraction) -------
__device__ __forceinline__ float area_fn(float x1, float y1, float x2, float y2) {
    return __fmul_rn(__fadd_rn(__fsub_rn(x2, x1), 1.0f),
                     __fadd_rn(__fsub_rn(y2, y1), 1.0f));
}

__device__ __forceinline__ float axis_best(float glo, float ghi,
                                           float olo, float ohi, int L, int R) {
    float t1 = __fmul_rn(__fsub_rn(glo, olo), 0.0625f);
    float t2 = __fmul_rn(__fsub_rn(ghi, ohi), 0.0625f);
    int f1 = (int)floorf(t1), f2 = (int)floorf(t2);
    int cand[6] = {f1 - 1, f1, f1 + 1, f2 - 1, f2, f2 + 1};
    float best = -1e30f;
#pragma unroll
    for (int i = 0; i < 6; i++) {
        int x = min(max(cand[i], L), R);
        float sx = __fmul_rn(16.0f, (float)x);
        float alo = __fadd_rn(sx, olo), ahi = __fadd_rn(sx, ohi);
        float iw = __fadd_rn(__fsub_rn(fminf(ahi, ghi), fmaxf(alo, glo)), 1.0f);
        best = fmaxf(best, iw);
    }
    return best;
}

__device__ __forceinline__ void compute_anchors(int H, int W,
                                                float4* sbx, int4* sb, int* Ntot) {
    const double ratios[3] = {0.5, 1.0, 2.0};
    const double scales[3] = {8.0, 16.0, 32.0};
    int nt = 0;
    for (int r = 0; r < 3; r++) {
        double ws = rint(sqrt(256.0 / ratios[r]));
        double hs = rint(ws * ratios[r]);
        for (int s = 0; s < 3; s++) {
            double Wd = ws * scales[s], Hd = hs * scales[s];
            int a = r * 3 + s;
            double x1 = 7.5 - 0.5 * (Wd - 1.0);
            double y1 = 7.5 - 0.5 * (Hd - 1.0);
            double x2 = 7.5 + 0.5 * (Wd - 1.0);
            double y2 = 7.5 + 0.5 * (Hd - 1.0);
            sbx[a] = make_float4((float)x1, (float)y1, (float)x2, (float)y2);
            int ix1 = (int)llrint(x1), iy1 = (int)llrint(y1);
            int ix2 = (int)llrint(x2), iy2 = (int)llrint(y2);
            int Lx = (ix1 < 0) ? ((-ix1 + 15) / 16) : 0;
            int Ly = (iy1 < 0) ? ((-iy1 + 15) / 16) : 0;
            int nxw = 16 * W - 1 - ix2;
            int nyh = 16 * H - 1 - iy2;
            int Rx = (nxw < 0) ? -1 : min(W - 1, nxw / 16);
            int Ry = (nyh < 0) ? -1 : min(H - 1, nyh / 16);
            sb[a] = make_int4(Lx, Rx, Ly, Ry);
            int nx = Rx - Lx + 1; if (nx < 0) nx = 0;
            int ny = Ry - Ly + 1; if (ny < 0) ny = 0;
            nt += nx * ny;
        }
    }
    *Ntot = nt;
}

// ------ K1: setup + rank + anchor compaction + analytic gt_max + zeroing -----
__global__ void k_grid(const float* __restrict__ gt,
                       const int* pB, const int* pG, const int* pH, const int* pW) {
    __shared__ int4 sb[A_NUM];
    __shared__ float4 sbx[A_NUM];
    __shared__ int sdim[5];  // H, W, KA, B, G
    int tid = threadIdx.x;
    if (tid == 0) {
        int H = *pH, W = *pW;
        int Ntot;
        compute_anchors(H, W, sbx, sb, &Ntot);
        int KA = H * W * A_NUM;
        if (KA > KA_MAX) KA = KA_MAX;
        int B = *pB, G = *pG;
        if (B > B_MAX) B = B_MAX;
        if (G > G_MAX) G = G_MAX;
        sdim[0] = H; sdim[1] = W; sdim[2] = KA; sdim[3] = B; sdim[4] = G;
        if (blockIdx.x == 0) {
            Params p; p.B = B; p.G = G; p.H = H; p.W = W; p.KA = KA; p.N = Ntot;
            g_p = p;
            for (int a = 0; a < A_NUM; a++) { g_abox[a] = sbx[a]; g_bnd[a] = sb[a]; }
        }
    }
    __syncthreads();
    int ka = blockIdx.x * blockDim.x + tid;
    if (blockIdx.x == 0 && tid < B_MAX) {
        uint32_t h0 = 0u, h1 = (uint32_t)tid;
        tf2x32(0u, 42u, h0, h1);
        uint32_t f0 = 0u, f1 = 0u; tf2x32(h0, h1, f0, f1);
        uint32_t c0 = 0u, c1 = 1u; tf2x32(h0, h1, c0, c1);
        g_keyf[tid * 2 + 0] = f0; g_keyf[tid * 2 + 1] = f1;
        g_keyb[tid * 2 + 0] = c0; g_keyb[tid * 2 + 1] = c1;
    }
    if (ka < B_MAX) { g_fgcnt[ka] = 0; g_bgcnt[ka] = 0; g_bgtot[ka] = 0; }
    const int B = sdim[3], G = sdim[4];
    // analytic per-gt max IoU
    if (ka < B_MAX * G_MAX) {
        int b = ka >> 6, g = ka & 63;
        float gm = 0.0f;
        if (b < B && g < G) {
            float4 gb = reinterpret_cast<const float4*>(gt)[(size_t)b * G + g];
            float areag = area_fn(gb.x, gb.y, gb.z, gb.w);
            for (int a = 0; a < A_NUM; a++) {
                int4 bb = sb[a];
                if (bb.y < bb.x || bb.w < bb.z) continue;
                float4 o = sbx[a];
                float bw = axis_best(gb.x, gb.z, o.x, o.z, bb.x, bb.y);
                float bh = axis_best(gb.y, gb.w, o.y, o.w, bb.z, bb.w);
                float iw = fmaxf(bw, 0.0f), ih = fmaxf(bh, 0.0f);
                float inter = __fmul_rn(iw, ih);
                if (inter > 0.0f) {
                    float areaa = area_fn(o.x, o.y, o.z, o.w);
                    float denom = __fsub_rn(__fadd_rn(areaa, areag), inter);
                    gm = fmaxf(gm, __fdiv_rn(inter, denom));
                }
            }
        }
        g_gtmaxf[ka] = gm;
    }
    const int W = sdim[1], KA = sdim[2];
    const int HW = sdim[0] * W;
    if (ka >= KA) return;
    int a = ka % A_NUM;
    int cell = ka / A_NUM;
    int x = cell % W, y = cell / W;
    int rank = 0;
#pragma unroll
    for (int a2 = 0; a2 < A_NUM; a2++) {
        int4 bb = sb[a2];
        int nx = bb.y - bb.x + 1; if (nx < 0) nx = 0;
        int rb = min(bb.w, y - 1) - bb.z + 1; if (rb < 0) rb = 0;
        rank += rb * nx;
        if (y >= bb.z && y <= bb.w) {
            int xb = min(bb.y, x - 1) - bb.x + 1; if (xb < 0) xb = 0;
            rank += xb;
            if (a2 < a && x >= bb.x && x <= bb.y) rank += 1;
        }
    }
    int4 mb = sb[a];
    bool inside = (x >= mb.x && x <= mb.y && y >= mb.z && y <= mb.w);
    if (inside) {
        float sx = __fmul_rn(16.0f, (float)x), sy = __fmul_rn(16.0f, (float)y);
        float4 o = sbx[a];
        g_anc4[rank] = make_float4(__fadd_rn(sx, o.x), __fadd_rn(sy, o.y),
                                   __fadd_rn(sx, o.z), __fadd_rn(sy, o.w));
        g_rank_t[a * HW + cell] = rank;
    } else {
        g_rank_t[a * HW + cell] = -1;
    }
}

// ------ K2: fused pass: best/arg + hit + labels + prio + pre-gather ----------
__global__ void k_passA(const float* __restrict__ gt) {
    int b = blockIdx.y;
    if (b >= g_p.B) return;
    const int N = g_p.N, G = g_p.G;
    int base = blockIdx.x * (256 * APT);
    if (base >= N) return;
    __shared__ float4 sgt[G_MAX];
    __shared__ float sga[G_MAX], sgm[G_MAX];
    __shared__ float4 cgt[G_MAX];
    __shared__ float cga[G_MAX], cgm[G_MAX];
    __shared__ unsigned char cgi[G_MAX];
    __shared__ int s_ymin, s_ymax, s_scnt, s_bgc;
    __shared__ unsigned s_bal[2];
    int tid = threadIdx.x;
    int lane = tid & 31;
    if (tid == 0) { s_ymin = 0x7f7fffff; s_ymax = 0; s_bgc = 0; }
    if (tid < G_MAX) {
        float4 gb;
        float gm = 0.0f;
        if (tid < G) {
            gb = reinterpret_cast<const float4*>(gt)[(size_t)b * G + tid];
            gm = g_gtmaxf[b * G_MAX + tid];
        } else {
            gb = make_float4(2e9f, 2e9f, -2e9f, -2e9f);
        }
        sgt[tid] = gb;
        sga[tid] = area_fn(gb.x, gb.y, gb.z, gb.w);
        sgm[tid] = gm;
    }
    __syncthreads();
    float4 A[APT]; float area[APT]; float best[APT]; int jarg[APT]; bool hit[APT]; bool val[APT];
    float ymn = 3e9f, ymx = -3e9f;
#pragma unroll
    for (int k = 0; k < APT; k++) {
        int idx = base + k * 256 + tid;
        val[k] = idx < N;
        A[k] = val[k] ? g_anc4[idx] : make_float4(3e9f, 3e9f, -3e9f, -3e9f);
        area[k] = area_fn(A[k].x, A[k].y, A[k].z, A[k].w);
        best[k] = 0.0f; jarg[k] = -1; hit[k] = false;
        ymn = fminf(ymn, A[k].y);
        ymx = fmaxf(ymx, A[k].w);
    }
#pragma unroll
    for (int off = 16; off > 0; off >>= 1) {
        ymn = fminf(ymn, __shfl_xor_sync(0xFFFFFFFFu, ymn, off));
        ymx = fmaxf(ymx, __shfl_xor_sync(0xFFFFFFFFu, ymx, off));
    }
    if (lane == 0) {
        atomicMin(&s_ymin, __float_as_int(ymn));
        atomicMax(&s_ymax, __float_as_int(ymx));
    }
    __syncthreads();
    float wlo = __int_as_float(s_ymin) - 4.0f;
    float whi = __int_as_float(s_ymax) + 4.0f;
    bool pass = false;
    unsigned bal = 0;
    if (tid < 64) {
        if (tid < G) {
            float4 gb = sgt[tid];
            pass = (gb.w >= wlo) && (gb.y <= whi);
        }
        bal = __ballot_sync(0xFFFFFFFFu, pass);
        if (lane == 0) s_bal[tid >> 5] = bal;
    }
    __syncthreads();
    if (tid < 64 && pass) {
        int w = tid >> 5;
        int off = __popc(bal & ((1u << lane) - 1u)) + (w ? __popc(s_bal[0]) : 0);
        cgt[off] = sgt[tid]; cga[off] = sga[tid]; cgm[off] = sgm[tid];
        cgi[off] = (unsigned char)tid;
    }
    if (tid == 0) s_scnt = __popc(s_bal[0]) + __popc(s_bal[1]);
    __syncthreads();
    int scnt = s_scnt;
    for (int j = 0; j < scnt; j++) {
        float4 gb = cgt[j]; float ag = cga[j]; float gm = cgm[j];
#pragma unroll
        for (int k = 0; k < APT; k++) {
            float iw = __fadd_rn(__fsub_rn(fminf(A[k].z, gb.z), fmaxf(A[k].x, gb.x)), 1.0f);
            float ih = __fadd_rn(__fsub_rn(fminf(A[k].w, gb.w), fmaxf(A[k].y, gb.y)), 1.0f);
            iw = fmaxf(iw, 0.0f);
            ih = fmaxf(ih, 0.0f);
            float inter = __fmul_rn(iw, ih);
            if (inter > 0.0f) {   // iou == +0 exactly when inter == 0
                float denom = __fsub_rn(__fadd_rn(area[k], ag), inter);
                float iou = __fdiv_rn(inter, denom);
                hit[k] |= (iou == gm);
                if (iou > best[k]) { best[k] = iou; jarg[k] = j; }
            }
        }
    }
    // epilogue: labels + threefry priority + candidate pre-gather + bg count
    uint32_t kf0 = g_keyf[b * 2], kf1 = g_keyf[b * 2 + 1];
    uint32_t kb0 = g_keyb[b * 2], kb1 = g_keyb[b * 2 + 1];
    int bgc = 0;
#pragma unroll
    for (int k = 0; k < APT; k++) {
        if (val[k]) {
            int idx = base + k * 256 + tid;
            int lab = -1;
            if (best[k] < 0.3f) lab = 0;
            if (best[k] >= 0.7f) lab = 1;
            if (hit[k]) lab = 1;
            g_arg[(size_t)b * N_MAX + idx] =
                (jarg[k] < 0) ? (unsigned char)0 : cgi[jarg[k]];
            uint32_t word = 0u;
            if (lab >= 0) {
                uint32_t q0 = (lab == 1) ? kf0 : kb0;
                uint32_t q1 = (lab == 1) ? kf1 : kb1;
                uint32_t c0 = 0u, c1 = (uint32_t)idx;
                tf2x32(q0, q1, c0, c1);
                uint32_t p = (c0 ^ c1) >> 9;
                word = (p << 2) | (uint32_t)(lab + 1);
                unsigned long long key =
                    ((unsigned long long)p << 16) | (unsigned)idx;
                if (lab == 1) {
                    int pos = atomicAdd(&g_fgcnt[b], 1);
                    if (pos < FGB) g_fgbuf[b][pos] = key;
                } else {
                    bgc++;
                    if ((p >> 15) < 8u) {
                        int pos = atomicAdd(&g_bgcnt[b], 1);
                        if (pos < BGB) g_bgbuf[b][pos] = key;
                    }
                }
            }
            g_lp[(size_t)b * N_MAX + idx] = word;
        }
    }
    // reduce bg count: warp then block then one global atomic
#pragma unroll
    for (int off = 16; off > 0; off >>= 1)
        bgc += __shfl_xor_sync(0xFFFFFFFFu, bgc, off);
    if (lane == 0 && bgc) atomicAdd(&s_bgc, bgc);
    __syncthreads();
    if (tid == 0 && s_bgc) atomicAdd(&g_bgtot[b], s_bgc);
}

// ---- shared-hist bin finder: 256 threads, hist[256] -> (bin, local k) -------
__device__ __forceinline__ void find_bin(int tid, const int* hist, int kk,
                                         int* s_out /* [2]: bin, lk */) {
    __shared__ int s_ws[8];
    int lane = tid & 31, w = tid >> 5;
    int c = hist[tid];
    int v = c;
#pragma unroll
    for (int o = 1; o < 32; o <<= 1) {
        int u = __shfl_up_sync(0xFFFFFFFFu, v, o);
        if (lane >= o) v += u;
    }
    if (lane == 31) s_ws[w] = v;
    __syncthreads();
    if (tid == 0) {
        int acc = 0;
        for (int i = 0; i < 8; i++) { acc += s_ws[i]; s_ws[i] = acc; }
    }
    __syncthreads();
    int cum = v + (w ? s_ws[w - 1] : 0);
    if (cum >= kk && cum - c < kk) {
        s_out[0] = tid;
        s_out[1] = kk - (cum - c);
    }
    __syncthreads();
}

// ------ K3: subsample thresholds, candidates-only ----------------------------
__global__ void k_select() {
    int b = blockIdx.x;
    if (b >= g_p.B) return;
    int tid = threadIdx.x;  // 256
    __shared__ int hist[256];
    __shared__ unsigned long long cand[SELB];
    __shared__ int s_c, s_bin[2];
    const int N = g_p.N;
    const uint32_t* lp = g_lp + (size_t)b * N_MAX;
    int fgtot = g_fgcnt[b];
    int bgin = g_bgcnt[b];
    int bgtot = g_bgtot[b];
    int numbg = 256 - min(fgtot, 128);
    // ---------------- fg threshold ----------------
    if (fgtot > 128) {
        bool ok = fgtot <= FGB;
        hist[tid] = 0;
        if (tid == 0) s_c = 0;
        __syncthreads();
        if (ok) {
            for (int i = tid; i < fgtot; i += 256)
                atomicAdd(&hist[(int)(g_fgbuf[b][i] >> 31) & 0xFF], 1);
        } else {
            for (int i = tid; i < N; i += 256) {
                uint32_t wd = lp[i];
                if ((wd & 3u) == 2u) atomicAdd(&hist[(wd >> 17) & 0xFFu], 1);
            }
        }
        __syncthreads();
        find_bin(tid, hist, 128, s_bin);
        int df = s_bin[0], lkf = s_bin[1];
        if (ok) {
            for (int i = tid; i < fgtot; i += 256) {
                unsigned long long key = g_fgbuf[b][i];
                if (((int)(key >> 31) & 0xFF) == df) {
                    int pos = atomicAdd(&s_c, 1);
                    if (pos < SELB) cand[pos] = key;
                }
            }
        } else {
            for (int i = tid; i < N; i += 256) {
                uint32_t wd = lp[i];
                if ((wd & 3u) == 2u && (int)((wd >> 17) & 0xFFu) == df) {
                    int pos = atomicAdd(&s_c, 1);
                    if (pos < SELB)
                        cand[pos] = ((unsigned long long)(wd >> 2) << 16) | (unsigned)i;
                }
            }
        }
        __syncthreads();
        int m = min(s_c, SELB);
        for (int i = tid; i < m; i += 256) {
            unsigned long long key = cand[i];
            int c = 0;
            for (int j = 0; j < m; j++) c += (cand[j] < key);
            if (c == lkf - 1) g_thr[b][0] = key;
        }
        __syncthreads();
    } else if (tid == 0) {
        g_thr[b][0] = ~0ull;
    }
    // ---------------- bg threshold ----------------
    if (bgtot > numbg) {
        bool ok = (bgin >= numbg) && (bgin <= BGB);  // guarantees db < 8
        hist[tid] = 0;
        if (tid == 0) s_c = 0;
        __syncthreads();
        if (ok) {
            for (int i = tid; i < bgin; i += 256)
                atomicAdd(&hist[(int)(g_bgbuf[b][i] >> 31) & 0xFF], 1);
        } else {
            for (int i = tid; i < N; i += 256) {
                uint32_t wd = lp[i];
                if ((wd & 3u) == 1u) atomicAdd(&hist[(wd >> 17) & 0xFFu], 1);
            }
        }
        __syncthreads();
        find_bin(tid, hist, numbg, s_bin);
        int db = s_bin[0], lkb = s_bin[1];
        if (ok) {
            for (int i = tid; i < bgin; i += 256) {
                unsigned long long key = g_bgbuf[b][i];
                if (((int)(key >> 31) & 0xFF) == db) {
                    int pos = atomicAdd(&s_c, 1);
                    if (pos < SELB) cand[pos] = key;
                }
            }
        } else {
            for (int i = tid; i < N; i += 256) {
                uint32_t wd = lp[i];
                if ((wd & 3u) == 1u && (int)((wd >> 17) & 0xFFu) == db) {
                    int pos = atomicAdd(&s_c, 1);
                    if (pos < SELB)
                        cand[pos] = ((unsigned long long)(wd >> 2) << 16) | (unsigned)i;
                }
            }
        }
        __syncthreads();
        int m = min(s_c, SELB);
        for (int i = tid; i < m; i += 256) {
            unsigned long long key = cand[i];
            int c = 0;
            for (int j = 0; j < m; j++) c += (cand[j] < key);
            if (c == lkb - 1) g_thr[b][1] = key;
        }
    } else if (tid == 0) {
        g_thr[b][1] = ~0ull;
    }
}

// ------ K4: fused zero+emit; labels + reg, all float4 stores -----------------
__global__ void k_emit(const float* __restrict__ gt, float* __restrict__ out) {
    int b = blockIdx.y;
    if (b >= g_p.B) return;
    const int H = g_p.H, W = g_p.W, HW = H * W, KA = g_p.KA, G = g_p.G, B = g_p.B;
    int q = blockIdx.x * blockDim.x + threadIdx.x;  // quad index
    int t0 = q * 4;
    if (t0 >= KA) return;
    int a = t0 / HW;            // HW divisible by 4 -> same a for whole quad
    int rem = t0 - a * HW;
    int4 rk = *reinterpret_cast<const int4*>(&g_rank_t[t0]);
    unsigned long long thrf = g_thr[b][0], thrb = g_thr[b][1];
    float lv[4];
    float4 rg[4] = {make_float4(0.f, 0.f, 0.f, 0.f), make_float4(0.f, 0.f, 0.f, 0.f),
                    make_float4(0.f, 0.f, 0.f, 0.f), make_float4(0.f, 0.f, 0.f, 0.f)};
    int rks[4] = {rk.x, rk.y, rk.z, rk.w};
#pragma unroll
    for (int j = 0; j < 4; j++) {
        int rank = rks[j];
        int l = -1;
        if (rank >= 0) {
            uint32_t wd = g_lp[(size_t)b * N_MAX + rank];
            l = (int)(wd & 3u) - 1;
            if (l >= 0) {
                unsigned long long key =
                    ((unsigned long long)(wd >> 2) << 16) | (unsigned)rank;
                if (key > (l == 1 ? thrf : thrb)) l = -1;
            }
        }
        lv[j] = (float)l;
        if (l == 1) {  // rare
            int arg = g_arg[(size_t)b * N_MAX + rank];
            float4 av = g_anc4[rank];
            const float* gp = gt + ((size_t)b * G + arg) * 4;
            float g0 = gp[0], g1 = gp[1], g2 = gp[2], g3 = gp[3];
            float aw = av.z - av.x + 1.0f, ah = av.w - av.y + 1.0f;
            float acx = av.x + 0.5f * (aw - 1.0f), acy = av.y + 0.5f * (ah - 1.0f);
            float gw = g2 - g0 + 1.0f, gh = g3 - g1 + 1.0f;
            float gcx = g0 + 0.5f * (gw - 1.0f), gcy = g1 + 0.5f * (gh - 1.0f);
            float r0 = (gcx - acx) / aw;
            float r1 = (gcy - acy) / ah;
            float r2 = logf(gw / aw);
            float r3 = logf(gh / ah);
            if (j == 0) { rg[0].x = r0; rg[1].x = r1; rg[2].x = r2; rg[3].x = r3; }
            if (j == 1) { rg[0].y = r0; rg[1].y = r1; rg[2].y = r2; rg[3].y = r3; }
            if (j == 2) { rg[0].z = r0; rg[1].z = r1; rg[2].z = r2; rg[3].z = r3; }
            if (j == 3) { rg[0].w = r0; rg[1].w = r1; rg[2].w = r2; rg[3].w = r3; }
        }
    }
    *reinterpret_cast<float4*>(&out[(size_t)b * A_NUM * HW + t0]) =
        make_float4(lv[0], lv[1], lv[2], lv[3]);
    float* out_reg = out + (size_t)B * A_NUM * HW;
    size_t rb = ((size_t)b * A_NUM * 4 + (size_t)a * 4) * HW + rem;
#pragma unroll
    for (int d = 0; d < 4; d++)
        *reinterpret_cast<float4*>(&out_reg[rb + (size_t)d * HW]) = rg[d];
}

extern "C" void kernel_launch(void* const* d_in, const int* in_sizes, int n_in,
                              void* d_out, int out_size) {
    const float* gt = (const float*)d_in[0];
    const int* pB = (const int*)d_in[1];
    const int* pG = (const int*)d_in[2];
    const int* pH = (const int*)d_in[3];
    const int* pW = (const int*)d_in[4];

    k_grid<<<(KA_MAX + 255) / 256, 256>>>(gt, pB, pG, pH, pW);
    {
        dim3 g((N_MAX + 256 * APT - 1) / (256 * APT), B_MAX);
        k_passA<<<g, 256>>>(gt);
    }
    k_select<<<B_MAX, 256>>>();
    {
        dim3 g((KA_MAX / 4 + 255) / 256, B_MAX);
        k_emit<<<g, 256>>>(gt, (float*)d_out);
    }
}